// round 16
// baseline (speedup 1.0000x reference)
#include <cuda_runtime.h>
#include <cuda_fp16.h>
#include <math.h>
#include <stdint.h>

// Problem constants
#define VOCAB   50257
#define VPAD    50304            // 393 * 128, 16B-aligned fp16 rows
#define KCTX    8
#define EMBED   64
#define HIDDEN  1024
#define BATCH   256
#define KE      (KCTX * EMBED)   // 512

// ---------------------------------------------------------------------------
__device__ __forceinline__ uint32_t smem_u32_of(const void* p) {
    uint32_t a;
    asm("{ .reg .u64 t; cvta.to.shared.u64 t, %1; cvt.u32.u64 %0, t; }" : "=r"(a) : "l"(p));
    return a;
}
__device__ __forceinline__ void cp_async16(uint32_t dst, const void* src) {
    asm volatile("cp.async.cg.shared.global [%0], [%1], 16;" :: "r"(dst), "l"(src) : "memory");
}
#define CP_COMMIT() asm volatile("cp.async.commit_group;" ::: "memory")
#define CP_WAIT(n)  asm volatile("cp.async.wait_group %0;" :: "n"(n) : "memory")

__device__ __forceinline__ void mma16816(float* d, const uint32_t* a, const uint32_t* b) {
    asm volatile(
        "mma.sync.aligned.m16n8k16.row.col.f32.f16.f16.f32 "
        "{%0,%1,%2,%3}, {%4,%5,%6,%7}, {%8,%9}, {%0,%1,%2,%3};"
        : "+f"(d[0]), "+f"(d[1]), "+f"(d[2]), "+f"(d[3])
        : "r"(a[0]), "r"(a[1]), "r"(a[2]), "r"(a[3]), "r"(b[0]), "r"(b[1]));
}

// ---------------------------------------------------------------------------
// Scratch
// ---------------------------------------------------------------------------
__device__ float  g_x0[BATCH * KE];
__device__ float  g_h1[BATCH * HIDDEN];
__device__ __half g_Ah[BATCH * HIDDEN];
__device__ __half g_W3h[(size_t)HIDDEN * VPAD];   // fp16 W3, padded rows

// ---------------------------------------------------------------------------
// Kernel 1: EARLY-EXIT one-hot scan + embedding gather (one block per row).
// ---------------------------------------------------------------------------
#define GRP 8
__global__ void __launch_bounds__(256)
embed_kernel(const float* __restrict__ ctx,
             const float* __restrict__ embed_w,
             float* __restrict__ x0)
{
    __shared__ volatile int s_found;
    __shared__ int   s_idx;
    __shared__ float s_val;
    if (threadIdx.x == 0) { s_found = 0; s_idx = 0; s_val = 0.0f; }
    __syncthreads();

    size_t off = (size_t)blockIdx.x * VOCAB;
    const float* row = ctx + off;
    int a0 = (int)((4 - (off & 3)) & 3);       // scalar prologue to 16B align

    for (int v = threadIdx.x; v < a0; v += 256) {
        float c = row[v];
        if (c != 0.0f) { s_idx = v; s_val = c; s_found = 1; }
    }
    const int nv4 = (VOCAB - a0) >> 2;
    const int nv4_main = nv4 & ~(256 * GRP - 1);   // whole groups
    const uint4* row4 = (const uint4*)(row + a0);

    for (int v0 = threadIdx.x; v0 < nv4_main; v0 += 256 * GRP) {
        if (s_found) break;                        // early exit: rest is zero
        uint4 u[GRP];
        #pragma unroll
        for (int j = 0; j < GRP; j++) u[j] = row4[v0 + 256 * j];
        #pragma unroll
        for (int j = 0; j < GRP; j++) {
            if (u[j].x | u[j].y | u[j].z | u[j].w) {
                int base = a0 + 4 * (v0 + 256 * j);
                if (u[j].x) { s_idx = base;     s_val = __uint_as_float(u[j].x); }
                if (u[j].y) { s_idx = base + 1; s_val = __uint_as_float(u[j].y); }
                if (u[j].z) { s_idx = base + 2; s_val = __uint_as_float(u[j].z); }
                if (u[j].w) { s_idx = base + 3; s_val = __uint_as_float(u[j].w); }
                s_found = 1;
            }
        }
    }
    if (!s_found) {
        for (int v = nv4_main + threadIdx.x; v < nv4; v += 256) {
            uint4 u = row4[v];
            if (u.x | u.y | u.z | u.w) {
                int base = a0 + 4 * v;
                if (u.x) { s_idx = base;     s_val = __uint_as_float(u.x); }
                if (u.y) { s_idx = base + 1; s_val = __uint_as_float(u.y); }
                if (u.z) { s_idx = base + 2; s_val = __uint_as_float(u.z); }
                if (u.w) { s_idx = base + 3; s_val = __uint_as_float(u.w); }
            }
        }
        for (int v = a0 + 4 * nv4 + threadIdx.x; v < VOCAB; v += 256) {
            float c = row[v];
            if (c != 0.0f) { s_idx = v; s_val = c; }
        }
    }
    __syncthreads();   // orders s_idx/s_val writes for all readers

    if (threadIdx.x < EMBED) {
        float e = embed_w[(size_t)s_idx * EMBED + threadIdx.x] * s_val;
        x0[(size_t)blockIdx.x * EMBED + threadIdx.x] = e;
    }
}

// ---------------------------------------------------------------------------
// W3 row converter (device fn): one fp32 row -> fp16 padded row.
// ---------------------------------------------------------------------------
__device__ __forceinline__ void convert_w3_row(const float* __restrict__ W3,
                                               __half* __restrict__ W3h, int row)
{
    const int tid = threadIdx.x;
    const float* src = W3 + (size_t)row * VOCAB;
    __half* dst = W3h + (size_t)row * VPAD;

    int c = tid;
    for (; c + 256 * 7 < VOCAB; c += 256 * 8) {
        float f0 = __ldg(src + c);
        float f1 = __ldg(src + c + 256);
        float f2 = __ldg(src + c + 512);
        float f3 = __ldg(src + c + 768);
        float f4 = __ldg(src + c + 1024);
        float f5 = __ldg(src + c + 1280);
        float f6 = __ldg(src + c + 1536);
        float f7 = __ldg(src + c + 1792);
        dst[c]        = __float2half_rn(f0);
        dst[c + 256]  = __float2half_rn(f1);
        dst[c + 512]  = __float2half_rn(f2);
        dst[c + 768]  = __float2half_rn(f3);
        dst[c + 1024] = __float2half_rn(f4);
        dst[c + 1280] = __float2half_rn(f5);
        dst[c + 1536] = __float2half_rn(f6);
        dst[c + 1792] = __float2half_rn(f7);
    }
    for (; c < VOCAB; c += 256) dst[c] = __float2half_rn(__ldg(src + c));
    for (int p = VOCAB + tid; p < VPAD; p += 256) dst[p] = __half(0.0f);
}

// ---------------------------------------------------------------------------
// Small-layer SGEMM (exact fp32), BK=32, register-prefetch double buffered.
// BM=16, BN=64, TM=1, TN=4, 256 threads -> 256 GEMM CTAs (~2/SM) so
// co-resident CTAs hide each other's barrier/LDS latency.
// Blocks with blockIdx.y >= M/16 are W3-converter blocks (2 rows each).
// ---------------------------------------------------------------------------
template<bool SILU, typename TO>
__global__ void __launch_bounds__(256)
sgemm_kernel(const float* __restrict__ A, const float* __restrict__ B,
             const float* __restrict__ bias, TO* __restrict__ C,
             int M, int N, int Kd,
             const float* __restrict__ W3, __half* __restrict__ W3h, int conv_row0)
{
    constexpr int BM = 16, BN = 64, BK = 32, TN = 4;
    const int gemm_y = M / BM;

    if ((int)blockIdx.y >= gemm_y) {   // ---- converter block ----
        int cb = (blockIdx.y - gemm_y) * gridDim.x + blockIdx.x;
        int row = conv_row0 + cb * 2;
        convert_w3_row(W3, W3h, row);
        convert_w3_row(W3, W3h, row + 1);
        return;
    }

    const int tid = threadIdx.x;
    const int tx  = tid & 15;                 // 0..15 along N
    const int ty  = tid >> 4;                 // 0..15 along M
    const int block_row = blockIdx.y * BM;
    const int block_col = blockIdx.x * BN;

    __shared__ float As[2][BK][BM + 1];
    __shared__ float Bs[2][BK][BN];

    // loaders: A = 16 rows x 8 float4 = 128 pieces (threads 0..127);
    //          B = 32 rows x 16 float4 = 512 pieces (2 per thread)
    const int a_row = tid >> 3, a_seg = tid & 7;
    const int b_row = tid >> 4, b_seg = tid & 15;

    float acc[TN];
    #pragma unroll
    for (int j = 0; j < TN; j++) acc[j] = 0.0f;

    float4 ra, rb0, rb1;
    auto ldg = [&](int k0) {
        if (tid < 128)
            ra = *(const float4*)(A + (size_t)(block_row + a_row) * Kd + k0 + a_seg * 4);
        rb0 = *(const float4*)(B + (size_t)(k0 + b_row)      * N + block_col + b_seg * 4);
        rb1 = *(const float4*)(B + (size_t)(k0 + b_row + 16) * N + block_col + b_seg * 4);
    };

    ldg(0);
    int buf = 0;
    for (int k0 = 0; k0 < Kd; k0 += BK, buf ^= 1) {
        if (tid < 128) {
            As[buf][a_seg * 4 + 0][a_row] = ra.x;
            As[buf][a_seg * 4 + 1][a_row] = ra.y;
            As[buf][a_seg * 4 + 2][a_row] = ra.z;
            As[buf][a_seg * 4 + 3][a_row] = ra.w;
        }
        *(float4*)&Bs[buf][b_row][b_seg * 4]      = rb0;
        *(float4*)&Bs[buf][b_row + 16][b_seg * 4] = rb1;
        __syncthreads();

        if (k0 + BK < Kd) ldg(k0 + BK);

        #pragma unroll
        for (int kk = 0; kk < BK; kk++) {
            float a = As[buf][kk][ty];
            float b_frag[TN];
            *(float4*)b_frag = *(const float4*)&Bs[buf][kk][tx * TN];
            #pragma unroll
            for (int j = 0; j < TN; j++)
                acc[j] += a * b_frag[j];
        }
    }

    {
        int m = block_row + ty;
        #pragma unroll
        for (int j = 0; j < TN; j++) {
            int n = block_col + tx * TN + j;
            float v = acc[j] + bias[n];
            if (SILU) v = v / (1.0f + expf(-v));
            if constexpr (sizeof(TO) == 2)
                C[(size_t)m * N + n] = __float2half_rn(v);
            else
                C[(size_t)m * N + n] = v;
        }
    }
}

// ---------------------------------------------------------------------------
// GEMM3: out[256, VOCAB] = Ah @ W3h + b3.  cp.async + HMMA pipeline.
// CTA: M=128 x N=128, 256 threads (8 warps: 4 M x 2 N), 4-stage pipeline,
// 2 CTAs/SM resident (R9 config, measured local optimum).
// ---------------------------------------------------------------------------
#define KC       32
#define NC       (HIDDEN / KC)             // 32
#define A_ROWB   80                         // 32 f16 (64B) + 16B pad
#define A_BYTES  (128 * A_ROWB)             // 10240
#define B_ROWB   272                        // 128 f16 (256B) + 16B pad
#define B_BYTES  (KC * B_ROWB)              // 8704
#define OFF_B    A_BYTES
#define STAGE_B  (A_BYTES + B_BYTES)        // 18944
#define NSTAGE   4
#define SMEM_G3  (NSTAGE * STAGE_B)         // 75776

__global__ void __launch_bounds__(256, 2)
gemm3_kernel(const __half* __restrict__ Ah, const __half* __restrict__ W3h,
             const float* __restrict__ bias, float* __restrict__ out)
{
    extern __shared__ __align__(16) char smem[];
    const uint32_t smb = smem_u32_of(smem);
    const int tid  = threadIdx.x;
    const int lane = tid & 31;
    const int wid  = tid >> 5;
    const int m0   = blockIdx.x * 128;  // 2 M tiles (fastest -> pair shares B)
    const int n0   = blockIdx.y * 128;  // 393 N tiles
    const int wm0  = (wid >> 1) * 32;   // 4 warps along M
    const int wn0  = (wid & 1) * 64;    // 2 warps along N

    float acc[2][8][4];
    #pragma unroll
    for (int i = 0; i < 2; i++)
        #pragma unroll
        for (int j = 0; j < 8; j++)
            #pragma unroll
            for (int q = 0; q < 4; q++) acc[i][j][q] = 0.0f;

    const uint32_t a_lm = (uint32_t)((wm0 + (lane & 15)) * A_ROWB + (lane >> 4) * 16);
    const uint32_t b_lm = (uint32_t)((lane & 15) * B_ROWB + (wn0 + (lane >> 4) * 8) * 2);

    auto stage = [&](int c) {
        const uint32_t bufb = smb + (uint32_t)(c % NSTAGE) * STAGE_B;
        #pragma unroll
        for (int h = 0; h < 2; h++) {
            int p = tid + 256 * h;
            int row = p >> 2, seg = p & 3;
            cp_async16(bufb + (uint32_t)(row * A_ROWB + seg * 16),
                       Ah + (size_t)(m0 + row) * HIDDEN + c * KC + seg * 8);
        }
        #pragma unroll
        for (int h = 0; h < 2; h++) {
            int p = tid + 256 * h;
            int row = p >> 4, seg = p & 15;
            cp_async16(bufb + OFF_B + (uint32_t)(row * B_ROWB + seg * 16),
                       W3h + (size_t)(c * KC + row) * VPAD + n0 + seg * 8);
        }
        CP_COMMIT();
    };

    auto compute = [&](int c) {
        const uint32_t bufb = smb + (uint32_t)(c % NSTAGE) * STAGE_B;
        #pragma unroll
        for (int ks = 0; ks < 2; ks++) {
            uint32_t bf[8][2];
            #pragma unroll
            for (int j = 0; j < 4; j++) {
                uint32_t addr = bufb + OFF_B + b_lm + ks * 16 * B_ROWB + j * 32;
                asm volatile(
                    "ldmatrix.sync.aligned.m8n8.x4.trans.shared.b16 {%0,%1,%2,%3}, [%4];"
                    : "=r"(bf[2*j][0]), "=r"(bf[2*j][1]), "=r"(bf[2*j+1][0]), "=r"(bf[2*j+1][1])
                    : "r"(addr));
            }
            uint32_t af[2][4];
            #pragma unroll
            for (int i = 0; i < 2; i++) {
                uint32_t addr = bufb + a_lm + i * 16 * A_ROWB + ks * 32;
                asm volatile(
                    "ldmatrix.sync.aligned.m8n8.x4.shared.b16 {%0,%1,%2,%3}, [%4];"
                    : "=r"(af[i][0]), "=r"(af[i][1]), "=r"(af[i][2]), "=r"(af[i][3])
                    : "r"(addr));
            }
            #pragma unroll
            for (int i = 0; i < 2; i++)
                #pragma unroll
                for (int j = 0; j < 8; j++)
                    mma16816(acc[i][j], af[i], bf[j]);
        }
    };

    stage(0);
    stage(1);
    stage(2);

    for (int c = 0; c < NC; c++) {
        if (c >= NC - 3) { CP_WAIT(0); }
        else             { CP_WAIT(2); }
        __syncthreads();
        compute(c);
        if (c + 3 < NC) stage(c + 3);
    }

    #pragma unroll
    for (int i = 0; i < 2; i++) {
        int m = m0 + wm0 + 16 * i + (lane >> 2);
        #pragma unroll
        for (int j = 0; j < 8; j++) {
            int n = n0 + wn0 + 8 * j + (lane & 3) * 2;
            if (n + 1 < VOCAB) {
                float b0 = __ldg(bias + n), b1 = __ldg(bias + n + 1);
                out[(size_t)m * VOCAB + n]           = acc[i][j][0] + b0;
                out[(size_t)m * VOCAB + n + 1]       = acc[i][j][1] + b1;
                out[(size_t)(m + 8) * VOCAB + n]     = acc[i][j][2] + b0;
                out[(size_t)(m + 8) * VOCAB + n + 1] = acc[i][j][3] + b1;
            } else if (n < VOCAB) {
                float b0 = __ldg(bias + n);
                out[(size_t)m * VOCAB + n]       = acc[i][j][0] + b0;
                out[(size_t)(m + 8) * VOCAB + n] = acc[i][j][2] + b0;
            }
        }
    }
}

// ---------------------------------------------------------------------------
extern "C" void kernel_launch(void* const* d_in, const int* in_sizes, int n_in,
                              void* d_out, int out_size)
{
    const float* ctx     = (const float*)d_in[0];
    const float* embed_w = (const float*)d_in[1];
    const float* W1      = (const float*)d_in[2];
    const float* b1      = (const float*)d_in[3];
    const float* W2      = (const float*)d_in[4];
    const float* b2      = (const float*)d_in[5];
    const float* W3      = (const float*)d_in[6];
    const float* b3      = (const float*)d_in[7];
    float*       out     = (float*)d_out;

    float *x0, *h1;
    __half *ah, *w3h;
    cudaGetSymbolAddress((void**)&x0,  g_x0);
    cudaGetSymbolAddress((void**)&h1,  g_h1);
    cudaGetSymbolAddress((void**)&ah,  g_Ah);
    cudaGetSymbolAddress((void**)&w3h, g_W3h);

    cudaFuncSetAttribute(gemm3_kernel,
                         cudaFuncAttributeMaxDynamicSharedMemorySize, SMEM_G3);

    // Phase 1: early-exit one-hot scan only (~239 MB expected traffic)
    embed_kernel<<<BATCH * KCTX, 256>>>(ctx, embed_w, x0);

    {   // layer 1 GEMM (y<16) + W3 convert rows [0,384) (y 16..27, 2 rows/blk)
        dim3 grid(HIDDEN / 64, BATCH / 16 + 384 / (2 * (HIDDEN / 64)));   // (16, 28)
        sgemm_kernel<true, float><<<grid, 256>>>(
            x0, W1, b1, h1, BATCH, HIDDEN, KE, W3, w3h, 0);
    }
    {   // layer 2 GEMM (fp16 out) + W3 convert rows [384,1024) (y 16..35)
        dim3 grid(HIDDEN / 64, BATCH / 16 + 640 / (2 * (HIDDEN / 64)));   // (16, 36)
        sgemm_kernel<true, __half><<<grid, 256>>>(
            h1, W2, b2, ah, BATCH, HIDDEN, HIDDEN, W3, w3h, 384);
    }

    gemm3_kernel<<<dim3(2, VPAD / 128), 256, SMEM_G3>>>(ah, w3h, b3, out);
}

// round 17
// speedup vs baseline: 1.1715x; 1.1715x over previous
#include <cuda_runtime.h>
#include <cuda_fp16.h>
#include <math.h>
#include <stdint.h>

// Problem constants
#define VOCAB   50257
#define VPAD    50304            // 393 * 128, 16B-aligned fp16 rows
#define KCTX    8
#define EMBED   64
#define HIDDEN  1024
#define BATCH   256
#define KE      (KCTX * EMBED)   // 512

// ---------------------------------------------------------------------------
__device__ __forceinline__ uint32_t smem_u32_of(const void* p) {
    uint32_t a;
    asm("{ .reg .u64 t; cvta.to.shared.u64 t, %1; cvt.u32.u64 %0, t; }" : "=r"(a) : "l"(p));
    return a;
}
__device__ __forceinline__ void cp_async16(uint32_t dst, const void* src) {
    asm volatile("cp.async.cg.shared.global [%0], [%1], 16;" :: "r"(dst), "l"(src) : "memory");
}
#define CP_COMMIT() asm volatile("cp.async.commit_group;" ::: "memory")
#define CP_WAIT(n)  asm volatile("cp.async.wait_group %0;" :: "n"(n) : "memory")

__device__ __forceinline__ void mma16816(float* d, const uint32_t* a, const uint32_t* b) {
    asm volatile(
        "mma.sync.aligned.m16n8k16.row.col.f32.f16.f16.f32 "
        "{%0,%1,%2,%3}, {%4,%5,%6,%7}, {%8,%9}, {%0,%1,%2,%3};"
        : "+f"(d[0]), "+f"(d[1]), "+f"(d[2]), "+f"(d[3])
        : "r"(a[0]), "r"(a[1]), "r"(a[2]), "r"(a[3]), "r"(b[0]), "r"(b[1]));
}

// ---------------------------------------------------------------------------
// Scratch
// ---------------------------------------------------------------------------
__device__ float  g_x0[BATCH * KE];
__device__ float  g_h1[BATCH * HIDDEN];
__device__ __half g_Ah[BATCH * HIDDEN];
__device__ __half g_W3h[(size_t)HIDDEN * VPAD];   // fp16 W3, padded rows

// ---------------------------------------------------------------------------
// Kernel 1: EARLY-EXIT one-hot scan + embedding gather (one block per row).
// ---------------------------------------------------------------------------
#define GRP 8
__global__ void __launch_bounds__(256)
embed_kernel(const float* __restrict__ ctx,
             const float* __restrict__ embed_w,
             float* __restrict__ x0)
{
    __shared__ volatile int s_found;
    __shared__ int   s_idx;
    __shared__ float s_val;
    if (threadIdx.x == 0) { s_found = 0; s_idx = 0; s_val = 0.0f; }
    __syncthreads();

    size_t off = (size_t)blockIdx.x * VOCAB;
    const float* row = ctx + off;
    int a0 = (int)((4 - (off & 3)) & 3);       // scalar prologue to 16B align

    for (int v = threadIdx.x; v < a0; v += 256) {
        float c = row[v];
        if (c != 0.0f) { s_idx = v; s_val = c; s_found = 1; }
    }
    const int nv4 = (VOCAB - a0) >> 2;
    const int nv4_main = nv4 & ~(256 * GRP - 1);   // whole groups
    const uint4* row4 = (const uint4*)(row + a0);

    for (int v0 = threadIdx.x; v0 < nv4_main; v0 += 256 * GRP) {
        if (s_found) break;                        // early exit: rest is zero
        uint4 u[GRP];
        #pragma unroll
        for (int j = 0; j < GRP; j++) u[j] = row4[v0 + 256 * j];
        #pragma unroll
        for (int j = 0; j < GRP; j++) {
            if (u[j].x | u[j].y | u[j].z | u[j].w) {
                int base = a0 + 4 * (v0 + 256 * j);
                if (u[j].x) { s_idx = base;     s_val = __uint_as_float(u[j].x); }
                if (u[j].y) { s_idx = base + 1; s_val = __uint_as_float(u[j].y); }
                if (u[j].z) { s_idx = base + 2; s_val = __uint_as_float(u[j].z); }
                if (u[j].w) { s_idx = base + 3; s_val = __uint_as_float(u[j].w); }
                s_found = 1;
            }
        }
    }
    if (!s_found) {
        for (int v = nv4_main + threadIdx.x; v < nv4; v += 256) {
            uint4 u = row4[v];
            if (u.x | u.y | u.z | u.w) {
                int base = a0 + 4 * v;
                if (u.x) { s_idx = base;     s_val = __uint_as_float(u.x); }
                if (u.y) { s_idx = base + 1; s_val = __uint_as_float(u.y); }
                if (u.z) { s_idx = base + 2; s_val = __uint_as_float(u.z); }
                if (u.w) { s_idx = base + 3; s_val = __uint_as_float(u.w); }
            }
        }
        for (int v = a0 + 4 * nv4 + threadIdx.x; v < VOCAB; v += 256) {
            float c = row[v];
            if (c != 0.0f) { s_idx = v; s_val = c; }
        }
    }
    __syncthreads();   // orders s_idx/s_val writes for all readers

    if (threadIdx.x < EMBED) {
        float e = embed_w[(size_t)s_idx * EMBED + threadIdx.x] * s_val;
        x0[(size_t)blockIdx.x * EMBED + threadIdx.x] = e;
    }
}

// ---------------------------------------------------------------------------
// W3 row converter (device fn): one fp32 row -> fp16 padded row.
// ---------------------------------------------------------------------------
__device__ __forceinline__ void convert_w3_row(const float* __restrict__ W3,
                                               __half* __restrict__ W3h, int row)
{
    const int tid = threadIdx.x;
    const float* src = W3 + (size_t)row * VOCAB;
    __half* dst = W3h + (size_t)row * VPAD;

    int c = tid;
    for (; c + 256 * 7 < VOCAB; c += 256 * 8) {
        float f0 = __ldg(src + c);
        float f1 = __ldg(src + c + 256);
        float f2 = __ldg(src + c + 512);
        float f3 = __ldg(src + c + 768);
        float f4 = __ldg(src + c + 1024);
        float f5 = __ldg(src + c + 1280);
        float f6 = __ldg(src + c + 1536);
        float f7 = __ldg(src + c + 1792);
        dst[c]        = __float2half_rn(f0);
        dst[c + 256]  = __float2half_rn(f1);
        dst[c + 512]  = __float2half_rn(f2);
        dst[c + 768]  = __float2half_rn(f3);
        dst[c + 1024] = __float2half_rn(f4);
        dst[c + 1280] = __float2half_rn(f5);
        dst[c + 1536] = __float2half_rn(f6);
        dst[c + 1792] = __float2half_rn(f7);
    }
    for (; c < VOCAB; c += 256) dst[c] = __float2half_rn(__ldg(src + c));
    for (int p = VOCAB + tid; p < VPAD; p += 256) dst[p] = __half(0.0f);
}

// ---------------------------------------------------------------------------
// Small-layer SGEMM (exact fp32), IN-BLOCK SPLIT-K.
// 256 threads = 2 groups of 128; group g covers K-half [g*Kd/2,(g+1)*Kd/2)
// with its own double-buffered smem + named barrier -> serial chunk chain
// halves, and the two groups hide each other's barrier/LDG latency.
// Tile BM=32 x BN=64; per group: 8x16 threads x (TM=4,TN=4).
// Blocks with blockIdx.y >= M/32 are W3-converter blocks (2 rows each).
// ---------------------------------------------------------------------------
template<bool SILU, typename TO>
__global__ void __launch_bounds__(256)
sgemm_kernel(const float* __restrict__ A, const float* __restrict__ B,
             const float* __restrict__ bias, TO* __restrict__ C,
             int M, int N, int Kd,
             const float* __restrict__ W3, __half* __restrict__ W3h, int conv_row0)
{
    constexpr int BM = 32, BN = 64, BK = 32, TM = 4, TN = 4;
    const int gemm_y = M / BM;

    if ((int)blockIdx.y >= gemm_y) {   // ---- converter block ----
        int cb = (blockIdx.y - gemm_y) * gridDim.x + blockIdx.x;
        int row = conv_row0 + cb * 2;
        convert_w3_row(W3, W3h, row);
        convert_w3_row(W3, W3h, row + 1);
        return;
    }

    __shared__ float As[2][2][BK][BM + 1];   // [group][buf]
    __shared__ float Bs[2][2][BK][BN];
    __shared__ float Part[BM][BN];           // group-1 partial sums

    const int tid = threadIdx.x;
    const int g   = tid >> 7;            // K-half group: 0 or 1
    const int lid = tid & 127;
    const int tx  = lid & 15;            // 0..15 along N (TN=4)
    const int ty  = lid >> 4;            // 0..7 along M (TM=4)
    const int block_row = blockIdx.y * BM;
    const int block_col = blockIdx.x * BN;
    const int khalf  = Kd >> 1;
    const int kbase  = g * khalf;
    const int nchunk = khalf / BK;       // 8 (K=512) or 16 (K=1024)

    // loaders (within the 128-thread group):
    // A chunk 32x32 = 256 float4 -> 2/thread: row=lid>>2, segs (lid&3), (lid&3)+4
    // B chunk 32x64 = 512 float4 -> 4/thread: rows (lid>>4)+8r, seg=lid&15
    const int a_row = lid >> 2, a_seg = lid & 3;
    const int b_row = lid >> 4, b_seg = lid & 15;

    float acc[TM][TN];
    #pragma unroll
    for (int i = 0; i < TM; i++)
        #pragma unroll
        for (int j = 0; j < TN; j++) acc[i][j] = 0.0f;

    float4 ra0, ra1, rb[4];
    auto ldg = [&](int k0) {
        const float* ap = A + (size_t)(block_row + a_row) * Kd + k0;
        ra0 = *(const float4*)(ap + a_seg * 4);
        ra1 = *(const float4*)(ap + (a_seg + 4) * 4);
        #pragma unroll
        for (int r = 0; r < 4; r++)
            rb[r] = *(const float4*)(B + (size_t)(k0 + b_row + 8 * r) * N
                                       + block_col + b_seg * 4);
    };

    ldg(kbase);
    int buf = 0;
    for (int c = 0; c < nchunk; c++, buf ^= 1) {
        // stash registers to smem (A transposed)
        #pragma unroll
        for (int e = 0; e < 4; e++) {
            As[g][buf][a_seg * 4 + e][a_row]       = (&ra0.x)[e];
            As[g][buf][(a_seg + 4) * 4 + e][a_row] = (&ra1.x)[e];
        }
        #pragma unroll
        for (int r = 0; r < 4; r++)
            *(float4*)&Bs[g][buf][b_row + 8 * r][b_seg * 4] = rb[r];
        asm volatile("bar.sync %0, 128;" :: "r"(g + 1) : "memory");

        if (c + 1 < nchunk) ldg(kbase + (c + 1) * BK);

        #pragma unroll
        for (int kk = 0; kk < BK; kk++) {
            float a_frag[TM], b_frag[TN];
            #pragma unroll
            for (int i = 0; i < TM; i++) a_frag[i] = As[g][buf][kk][ty * TM + i];
            *(float4*)b_frag = *(const float4*)&Bs[g][buf][kk][tx * TN];
            #pragma unroll
            for (int i = 0; i < TM; i++)
                #pragma unroll
                for (int j = 0; j < TN; j++)
                    acc[i][j] += a_frag[i] * b_frag[j];
        }
    }

    // group 1 publishes partials; group 0 combines + epilogue
    if (g == 1) {
        #pragma unroll
        for (int i = 0; i < TM; i++)
            *(float4*)&Part[ty * TM + i][tx * TN] = *(float4*)acc[i];
    }
    __syncthreads();
    if (g == 0) {
        #pragma unroll
        for (int i = 0; i < TM; i++) {
            int m = block_row + ty * TM + i;
            float4 p = *(float4*)&Part[ty * TM + i][tx * TN];
            #pragma unroll
            for (int j = 0; j < TN; j++) {
                int n = block_col + tx * TN + j;
                float v = acc[i][j] + (&p.x)[j] + bias[n];
                if (SILU) v = v / (1.0f + expf(-v));
                if constexpr (sizeof(TO) == 2)
                    C[(size_t)m * N + n] = __float2half_rn(v);
                else
                    C[(size_t)m * N + n] = v;
            }
        }
    }
}

// ---------------------------------------------------------------------------
// GEMM3: out[256, VOCAB] = Ah @ W3h + b3.  cp.async + HMMA pipeline.
// CTA: M=128 x N=128, 256 threads (8 warps: 4 M x 2 N), 4-stage pipeline,
// 2 CTAs/SM resident (R9 config, measured local optimum).
// ---------------------------------------------------------------------------
#define KC       32
#define NC       (HIDDEN / KC)             // 32
#define A_ROWB   80                         // 32 f16 (64B) + 16B pad
#define A_BYTES  (128 * A_ROWB)             // 10240
#define B_ROWB   272                        // 128 f16 (256B) + 16B pad
#define B_BYTES  (KC * B_ROWB)              // 8704
#define OFF_B    A_BYTES
#define STAGE_B  (A_BYTES + B_BYTES)        // 18944
#define NSTAGE   4
#define SMEM_G3  (NSTAGE * STAGE_B)         // 75776

__global__ void __launch_bounds__(256, 2)
gemm3_kernel(const __half* __restrict__ Ah, const __half* __restrict__ W3h,
             const float* __restrict__ bias, float* __restrict__ out)
{
    extern __shared__ __align__(16) char smem[];
    const uint32_t smb = smem_u32_of(smem);
    const int tid  = threadIdx.x;
    const int lane = tid & 31;
    const int wid  = tid >> 5;
    const int m0   = blockIdx.x * 128;  // 2 M tiles (fastest -> pair shares B)
    const int n0   = blockIdx.y * 128;  // 393 N tiles
    const int wm0  = (wid >> 1) * 32;   // 4 warps along M
    const int wn0  = (wid & 1) * 64;    // 2 warps along N

    float acc[2][8][4];
    #pragma unroll
    for (int i = 0; i < 2; i++)
        #pragma unroll
        for (int j = 0; j < 8; j++)
            #pragma unroll
            for (int q = 0; q < 4; q++) acc[i][j][q] = 0.0f;

    const uint32_t a_lm = (uint32_t)((wm0 + (lane & 15)) * A_ROWB + (lane >> 4) * 16);
    const uint32_t b_lm = (uint32_t)((lane & 15) * B_ROWB + (wn0 + (lane >> 4) * 8) * 2);

    auto stage = [&](int c) {
        const uint32_t bufb = smb + (uint32_t)(c % NSTAGE) * STAGE_B;
        #pragma unroll
        for (int h = 0; h < 2; h++) {
            int p = tid + 256 * h;
            int row = p >> 2, seg = p & 3;
            cp_async16(bufb + (uint32_t)(row * A_ROWB + seg * 16),
                       Ah + (size_t)(m0 + row) * HIDDEN + c * KC + seg * 8);
        }
        #pragma unroll
        for (int h = 0; h < 2; h++) {
            int p = tid + 256 * h;
            int row = p >> 4, seg = p & 15;
            cp_async16(bufb + OFF_B + (uint32_t)(row * B_ROWB + seg * 16),
                       W3h + (size_t)(c * KC + row) * VPAD + n0 + seg * 8);
        }
        CP_COMMIT();
    };

    auto compute = [&](int c) {
        const uint32_t bufb = smb + (uint32_t)(c % NSTAGE) * STAGE_B;
        #pragma unroll
        for (int ks = 0; ks < 2; ks++) {
            uint32_t bf[8][2];
            #pragma unroll
            for (int j = 0; j < 4; j++) {
                uint32_t addr = bufb + OFF_B + b_lm + ks * 16 * B_ROWB + j * 32;
                asm volatile(
                    "ldmatrix.sync.aligned.m8n8.x4.trans.shared.b16 {%0,%1,%2,%3}, [%4];"
                    : "=r"(bf[2*j][0]), "=r"(bf[2*j][1]), "=r"(bf[2*j+1][0]), "=r"(bf[2*j+1][1])
                    : "r"(addr));
            }
            uint32_t af[2][4];
            #pragma unroll
            for (int i = 0; i < 2; i++) {
                uint32_t addr = bufb + a_lm + i * 16 * A_ROWB + ks * 32;
                asm volatile(
                    "ldmatrix.sync.aligned.m8n8.x4.shared.b16 {%0,%1,%2,%3}, [%4];"
                    : "=r"(af[i][0]), "=r"(af[i][1]), "=r"(af[i][2]), "=r"(af[i][3])
                    : "r"(addr));
            }
            #pragma unroll
            for (int i = 0; i < 2; i++)
                #pragma unroll
                for (int j = 0; j < 8; j++)
                    mma16816(acc[i][j], af[i], bf[j]);
        }
    };

    stage(0);
    stage(1);
    stage(2);

    for (int c = 0; c < NC; c++) {
        if (c >= NC - 3) { CP_WAIT(0); }
        else             { CP_WAIT(2); }
        __syncthreads();
        compute(c);
        if (c + 3 < NC) stage(c + 3);
    }

    #pragma unroll
    for (int i = 0; i < 2; i++) {
        int m = m0 + wm0 + 16 * i + (lane >> 2);
        #pragma unroll
        for (int j = 0; j < 8; j++) {
            int n = n0 + wn0 + 8 * j + (lane & 3) * 2;
            if (n + 1 < VOCAB) {
                float b0 = __ldg(bias + n), b1 = __ldg(bias + n + 1);
                out[(size_t)m * VOCAB + n]           = acc[i][j][0] + b0;
                out[(size_t)m * VOCAB + n + 1]       = acc[i][j][1] + b1;
                out[(size_t)(m + 8) * VOCAB + n]     = acc[i][j][2] + b0;
                out[(size_t)(m + 8) * VOCAB + n + 1] = acc[i][j][3] + b1;
            } else if (n < VOCAB) {
                float b0 = __ldg(bias + n);
                out[(size_t)m * VOCAB + n]       = acc[i][j][0] + b0;
                out[(size_t)(m + 8) * VOCAB + n] = acc[i][j][2] + b0;
            }
        }
    }
}

// ---------------------------------------------------------------------------
extern "C" void kernel_launch(void* const* d_in, const int* in_sizes, int n_in,
                              void* d_out, int out_size)
{
    const float* ctx     = (const float*)d_in[0];
    const float* embed_w = (const float*)d_in[1];
    const float* W1      = (const float*)d_in[2];
    const float* b1      = (const float*)d_in[3];
    const float* W2      = (const float*)d_in[4];
    const float* b2      = (const float*)d_in[5];
    const float* W3      = (const float*)d_in[6];
    const float* b3      = (const float*)d_in[7];
    float*       out     = (float*)d_out;

    float *x0, *h1;
    __half *ah, *w3h;
    cudaGetSymbolAddress((void**)&x0,  g_x0);
    cudaGetSymbolAddress((void**)&h1,  g_h1);
    cudaGetSymbolAddress((void**)&ah,  g_Ah);
    cudaGetSymbolAddress((void**)&w3h, g_W3h);

    cudaFuncSetAttribute(gemm3_kernel,
                         cudaFuncAttributeMaxDynamicSharedMemorySize, SMEM_G3);

    // Phase 1: early-exit one-hot scan only (~239 MB expected traffic)
    embed_kernel<<<BATCH * KCTX, 256>>>(ctx, embed_w, x0);

    {   // layer 1 GEMM (y<8) + W3 convert rows [0,384) (y 8..19, 2 rows/block)
        dim3 grid(HIDDEN / 64, BATCH / 32 + 384 / (2 * (HIDDEN / 64)));   // (16, 20)
        sgemm_kernel<true, float><<<grid, 256>>>(
            x0, W1, b1, h1, BATCH, HIDDEN, KE, W3, w3h, 0);
    }
    {   // layer 2 GEMM (fp16 out) + W3 convert rows [384,1024) (y 8..27)
        dim3 grid(HIDDEN / 64, BATCH / 32 + 640 / (2 * (HIDDEN / 64)));   // (16, 28)
        sgemm_kernel<true, __half><<<grid, 256>>>(
            h1, W2, b2, ah, BATCH, HIDDEN, HIDDEN, W3, w3h, 384);
    }

    gemm3_kernel<<<dim3(2, VPAD / 128), 256, SMEM_G3>>>(ah, w3h, b3, out);
}